// round 2
// baseline (speedup 1.0000x reference)
#include <cuda_runtime.h>
#include <cstdint>

#define H 64
#define NMAX 100096
#define EMAX 2000000

// ---------------- static scratch (allocation-free) ----------------
__device__ float g_x [NMAX * H];   // gathered input features
__device__ float g_yl[NMAX * H];   // x @ Wl^T   (per layer, reused)
__device__ float g_yr[NMAX * H];   // x @ Wr^T   (per layer, reused)
__device__ float g_h [NMAX * H];   // layer-1 output
__device__ float g_h2[NMAX * H];   // layer-2 output
__device__ int   g_degi[NMAX];
__device__ int   g_off [NMAX];
__device__ int   g_cur [NMAX];
__device__ float g_inv [NMAX];
__device__ int   g_csr [EMAX];

// ---------------- prologue: gather x, zero degree ----------------
__global__ void prep_kernel(const float4* __restrict__ emb,
                            const int* __restrict__ nid, int n) {
    unsigned t = blockIdx.x * blockDim.x + threadIdx.x;
    unsigned i = t >> 4, q = t & 15;
    if (i < (unsigned)n) {
        int src = __ldg(nid + i);
        ((float4*)g_x)[(size_t)i * 16 + q] = emb[(size_t)src * 16 + q];
    }
    if (t < (unsigned)n) g_degi[t] = 0;
}

__global__ void deg_kernel(const int* __restrict__ ei, int E) {
    unsigned e = blockIdx.x * blockDim.x + threadIdx.x;
    if (e >= (unsigned)E) return;
    atomicAdd(&g_degi[__ldg(ei + E + e)], 1);
}

// single-block exclusive scan over degrees -> offsets, cursors, 1/deg
__global__ void scan_kernel(int n) {
    __shared__ int sm[1024];
    int tid = threadIdx.x;
    int chunk = (n + 1023) >> 10;
    int lo = tid * chunk, hi = min(lo + chunk, n);
    int s = 0;
    for (int j = lo; j < hi; j++) s += g_degi[j];
    sm[tid] = s;
    __syncthreads();
    for (int d = 1; d < 1024; d <<= 1) {
        int v = (tid >= d) ? sm[tid - d] : 0;
        __syncthreads();
        sm[tid] += v;
        __syncthreads();
    }
    int run = (tid == 0) ? 0 : sm[tid - 1];
    for (int j = lo; j < hi; j++) {
        int dg = g_degi[j];
        g_off[j] = run;
        g_cur[j] = run;
        g_inv[j] = 1.0f / fmaxf((float)dg, 1.0f);
        run += dg;
    }
}

__global__ void csr_kernel(const int* __restrict__ ei, int E) {
    unsigned e = blockIdx.x * blockDim.x + threadIdx.x;
    if (e >= (unsigned)E) return;
    int s = __ldg(ei + e);
    int d = __ldg(ei + E + e);
    int pos = atomicAdd(&g_cur[d], 1);
    g_csr[pos] = s;
}

// ---------------- dense transform: yl = x @ Wl^T, yr = x @ Wr^T -------------
// 4 nodes per warp: one LDS.128 weight load feeds 16 FFMAs.
template <int LAYER>
__global__ __launch_bounds__(256) void gemm_kernel(const float* __restrict__ Wl,
                                                   const float* __restrict__ Wr,
                                                   int n) {
    __shared__ float4 W4[64 * 32];          // W4[h*32+l] = Wl[2l][h],Wl[2l+1][h],Wr[2l][h],Wr[2l+1][h]
    __shared__ float  rb[8][4][64];         // staged x rows, 4 per warp

    const float* __restrict__ xin = (LAYER == 1) ? g_x : g_h;
    int tid = threadIdx.x;
    for (int i = tid; i < 64 * 32; i += 256) {
        int h = i >> 5, l = i & 31;
        W4[i] = make_float4(Wl[(2 * l) * 64 + h], Wl[(2 * l + 1) * 64 + h],
                            Wr[(2 * l) * 64 + h], Wr[(2 * l + 1) * 64 + h]);
    }
    __syncthreads();

    int warp = tid >> 5, lane = tid & 31;
    int base = (blockIdx.x * 8 + warp) * 4;

    float2* rb2 = (float2*)rb[warp];        // [4][32] float2 view
#pragma unroll
    for (int m = 0; m < 4; m++) {
        int v = base + m;
        float2 xv = (v < n) ? ((const float2*)xin)[(size_t)v * 32 + lane]
                            : make_float2(0.f, 0.f);
        rb2[m * 32 + lane] = xv;
    }
    __syncwarp();

    float2 aL[4], aR[4];
#pragma unroll
    for (int m = 0; m < 4; m++) { aL[m] = make_float2(0.f, 0.f); aR[m] = make_float2(0.f, 0.f); }

#pragma unroll
    for (int h = 0; h < 64; h++) {
        float4 w = W4[h * 32 + lane];
#pragma unroll
        for (int m = 0; m < 4; m++) {
            float xv = rb[warp][m][h];
            aL[m].x += xv * w.x; aL[m].y += xv * w.y;
            aR[m].x += xv * w.z; aR[m].y += xv * w.w;
        }
    }

    float2* yl2 = (float2*)g_yl;
    float2* yr2 = (float2*)g_yr;
#pragma unroll
    for (int m = 0; m < 4; m++) {
        int v = base + m;
        if (v < n) {
            yl2[(size_t)v * 32 + lane] = aL[m];
            yr2[(size_t)v * 32 + lane] = aR[m];
        }
    }
}

// ---------------- aggregation epilogue: out = act(mean_j yl_j + yr_v + b) ----
template <int LAYER>
__global__ __launch_bounds__(256) void agg_kernel(const float* __restrict__ bias,
                                                  int n) {
    int tid = threadIdx.x;
    int warp = tid >> 5, lane = tid & 31;
    int v = blockIdx.x * 8 + warp;
    if (v >= n) return;

    const float2* __restrict__ yl = (const float2*)g_yl;
    int beg = g_off[v], deg = g_degi[v], end = beg + deg;

    float2 acc = make_float2(0.f, 0.f);
    int j = beg;
    while (j + 32 <= end) {
        int idx = __ldg(g_csr + j + lane);
#pragma unroll
        for (int k = 0; k < 32; k++) {
            int s = __shfl_sync(0xffffffffu, idx, k);
            float2 t = yl[(size_t)s * 32 + lane];
            acc.x += t.x; acc.y += t.y;
        }
        j += 32;
    }
    if (j < end) {
        int nb = end - j;
        int idx = __ldg(g_csr + min(j + lane, end - 1));
        for (int k = 0; k < nb; k++) {
            int s = __shfl_sync(0xffffffffu, idx, k);
            float2 t = yl[(size_t)s * 32 + lane];
            acc.x += t.x; acc.y += t.y;
        }
    }

    float inv = g_inv[v];
    float2 yr = ((const float2*)g_yr)[(size_t)v * 32 + lane];
    float2 b2 = make_float2(bias[2 * lane], bias[2 * lane + 1]);
    float2 o;
    o.x = acc.x * inv + yr.x + b2.x;
    o.y = acc.y * inv + yr.y + b2.y;
    if (LAYER == 1) { o.x = fmaxf(o.x, 0.f); o.y = fmaxf(o.y, 0.f); }
    float2* out = (float2*)((LAYER == 1) ? g_h : g_h2);
    out[(size_t)v * 32 + lane] = o;
}

// ---------------- edge-dot classifier ----------------
__global__ void edge_dot_kernel(const int* __restrict__ ei,
                                float* __restrict__ out, int E) {
    unsigned t = blockIdx.x * blockDim.x + threadIdx.x;
    unsigned e = t >> 3, q = t & 7;
    if (e >= (unsigned)E) return;
    int s = __ldg(ei + e);
    int d = __ldg(ei + E + e);
    const float4* hs = (const float4*)g_h2 + (size_t)s * 16;
    const float4* hd = (const float4*)g_h2 + (size_t)d * 16;
    float4 a0 = hs[2 * q], a1 = hs[2 * q + 1];
    float4 c0 = hd[2 * q], c1 = hd[2 * q + 1];
    float sum = a0.x * c0.x + a0.y * c0.y + a0.z * c0.z + a0.w * c0.w
              + a1.x * c1.x + a1.y * c1.y + a1.z * c1.z + a1.w * c1.w;
    sum += __shfl_xor_sync(0xffffffffu, sum, 1);
    sum += __shfl_xor_sync(0xffffffffu, sum, 2);
    sum += __shfl_xor_sync(0xffffffffu, sum, 4);
    if (q == 0) out[e] = sum;
}

// ---------------- launch ----------------
extern "C" void kernel_launch(void* const* d_in, const int* in_sizes, int n_in,
                              void* d_out, int out_size) {
    const float* emb = (const float*)d_in[0];
    const float* Wl1 = (const float*)d_in[1];
    const float* Wr1 = (const float*)d_in[2];
    const float* b1  = (const float*)d_in[3];
    const float* Wl2 = (const float*)d_in[4];
    const float* Wr2 = (const float*)d_in[5];
    const float* b2  = (const float*)d_in[6];
    const int*   nid = (const int*)d_in[7];
    const int*   ei  = (const int*)d_in[8];
    float* out = (float*)d_out;

    int n = in_sizes[0] / H;       // 100000
    int E = in_sizes[8] / 2;       // 1600000

    unsigned thr = 256;
    unsigned pb  = ((unsigned)n * 16 + thr - 1) / thr;
    unsigned eb  = ((unsigned)E + thr - 1) / thr;
    unsigned gmb = ((unsigned)n + 31) / 32;          // 4 nodes/warp, 8 warps/block
    unsigned agb = ((unsigned)n + 7) / 8;            // 1 node/warp
    unsigned db  = ((unsigned)E * 8 + thr - 1) / thr;

    prep_kernel<<<pb, thr>>>((const float4*)emb, nid, n);
    deg_kernel<<<eb, thr>>>(ei, E);
    scan_kernel<<<1, 1024>>>(n);
    csr_kernel<<<eb, thr>>>(ei, E);

    gemm_kernel<1><<<gmb, thr>>>(Wl1, Wr1, n);
    agg_kernel<1><<<agb, thr>>>(b1, n);

    gemm_kernel<2><<<gmb, thr>>>(Wl2, Wr2, n);
    agg_kernel<2><<<agb, thr>>>(b2, n);

    edge_dot_kernel<<<db, thr>>>(ei, out, E);
}

// round 3
// speedup vs baseline: 1.5748x; 1.5748x over previous
#include <cuda_runtime.h>
#include <cstdint>

#define H 64
#define NMAX 100096
#define EMAX 2000000

// ---------------- static scratch (allocation-free) ----------------
__device__ float g_x [NMAX * H];   // gathered input features
__device__ float g_yl[NMAX * H];   // x @ Wl^T   (per layer, reused)
__device__ float g_yr[NMAX * H];   // x @ Wr^T   (per layer, reused)
__device__ float g_h [NMAX * H];   // layer-1 output
__device__ float g_h2[NMAX * H];   // layer-2 output
__device__ int   g_degi[NMAX];
__device__ int   g_off [NMAX];
__device__ int   g_cur [NMAX];
__device__ float g_inv [NMAX];
__device__ int   g_csr [EMAX];
__device__ int   g_total;

// ---------------- prologue: gather x, zero degree ----------------
__global__ void prep_kernel(const float4* __restrict__ emb,
                            const int* __restrict__ nid, int n) {
    unsigned t = blockIdx.x * blockDim.x + threadIdx.x;
    unsigned i = t >> 4, q = t & 15;
    if (i < (unsigned)n) {
        int src = __ldg(nid + i);
        ((float4*)g_x)[(size_t)i * 16 + q] = emb[(size_t)src * 16 + q];
    }
    if (t < (unsigned)n) g_degi[t] = 0;
    if (t == 0) g_total = 0;
}

__global__ void deg_kernel(const int* __restrict__ ei, int E) {
    unsigned e = blockIdx.x * blockDim.x + threadIdx.x;
    if (e >= (unsigned)E) return;
    atomicAdd(&g_degi[__ldg(ei + E + e)], 1);
}

// parallel CSR offset allocation: warp shfl-scan + one global atomic per warp.
// Offsets are disjoint but NOT node-ordered -- aggregation doesn't care.
__global__ void alloc_kernel(int n) {
    int i = blockIdx.x * blockDim.x + threadIdx.x;
    int lane = threadIdx.x & 31;
    int deg = (i < n) ? g_degi[i] : 0;
    int s = deg;
#pragma unroll
    for (int d = 1; d < 32; d <<= 1) {
        int v = __shfl_up_sync(0xffffffffu, s, d);
        if (lane >= d) s += v;
    }
    int wtot = __shfl_sync(0xffffffffu, s, 31);
    int base = 0;
    if (lane == 31) base = atomicAdd(&g_total, wtot);
    base = __shfl_sync(0xffffffffu, base, 31);
    int off = base + s - deg;
    if (i < n) {
        g_off[i] = off;
        g_cur[i] = off;
        g_inv[i] = 1.0f / fmaxf((float)deg, 1.0f);
    }
}

__global__ void csr_kernel(const int* __restrict__ ei, int E) {
    unsigned e = blockIdx.x * blockDim.x + threadIdx.x;
    if (e >= (unsigned)E) return;
    int s = __ldg(ei + e);
    int d = __ldg(ei + E + e);
    int pos = atomicAdd(&g_cur[d], 1);
    g_csr[pos] = s;
}

// ---------------- dense transform: yl = x @ Wl^T, yr = x @ Wr^T -------------
// 4 nodes per warp: one LDS.128 weight load feeds 16 FFMAs.
template <int LAYER>
__global__ __launch_bounds__(256) void gemm_kernel(const float* __restrict__ Wl,
                                                   const float* __restrict__ Wr,
                                                   int n) {
    __shared__ float4 W4[64 * 32];
    __shared__ float  rb[8][4][64];

    const float* __restrict__ xin = (LAYER == 1) ? g_x : g_h;
    int tid = threadIdx.x;
    for (int i = tid; i < 64 * 32; i += 256) {
        int h = i >> 5, l = i & 31;
        W4[i] = make_float4(Wl[(2 * l) * 64 + h], Wl[(2 * l + 1) * 64 + h],
                            Wr[(2 * l) * 64 + h], Wr[(2 * l + 1) * 64 + h]);
    }
    __syncthreads();

    int warp = tid >> 5, lane = tid & 31;
    int base = (blockIdx.x * 8 + warp) * 4;

    float2* rb2 = (float2*)rb[warp];
#pragma unroll
    for (int m = 0; m < 4; m++) {
        int v = base + m;
        float2 xv = (v < n) ? ((const float2*)xin)[(size_t)v * 32 + lane]
                            : make_float2(0.f, 0.f);
        rb2[m * 32 + lane] = xv;
    }
    __syncwarp();

    float2 aL[4], aR[4];
#pragma unroll
    for (int m = 0; m < 4; m++) { aL[m] = make_float2(0.f, 0.f); aR[m] = make_float2(0.f, 0.f); }

#pragma unroll
    for (int h = 0; h < 64; h++) {
        float4 w = W4[h * 32 + lane];
#pragma unroll
        for (int m = 0; m < 4; m++) {
            float xv = rb[warp][m][h];
            aL[m].x += xv * w.x; aL[m].y += xv * w.y;
            aR[m].x += xv * w.z; aR[m].y += xv * w.w;
        }
    }

    float2* yl2 = (float2*)g_yl;
    float2* yr2 = (float2*)g_yr;
#pragma unroll
    for (int m = 0; m < 4; m++) {
        int v = base + m;
        if (v < n) {
            yl2[(size_t)v * 32 + lane] = aL[m];
            yr2[(size_t)v * 32 + lane] = aR[m];
        }
    }
}

// ---------------- aggregation epilogue: out = act(mean_j yl_j + yr_v + b) ----
template <int LAYER>
__global__ __launch_bounds__(256) void agg_kernel(const float* __restrict__ bias,
                                                  int n) {
    int tid = threadIdx.x;
    int warp = tid >> 5, lane = tid & 31;
    int v = blockIdx.x * 8 + warp;
    if (v >= n) return;

    const float2* __restrict__ yl = (const float2*)g_yl;
    int beg = g_off[v], deg = g_degi[v], end = beg + deg;

    float2 acc = make_float2(0.f, 0.f);
    int j = beg;
    while (j + 32 <= end) {
        int idx = __ldg(g_csr + j + lane);
#pragma unroll
        for (int k = 0; k < 32; k++) {
            int s = __shfl_sync(0xffffffffu, idx, k);
            float2 t = yl[(size_t)s * 32 + lane];
            acc.x += t.x; acc.y += t.y;
        }
        j += 32;
    }
    if (j < end) {
        int nb = end - j;
        int idx = __ldg(g_csr + min(j + lane, end - 1));
        for (int k = 0; k < nb; k++) {
            int s = __shfl_sync(0xffffffffu, idx, k);
            float2 t = yl[(size_t)s * 32 + lane];
            acc.x += t.x; acc.y += t.y;
        }
    }

    float inv = g_inv[v];
    float2 yr = ((const float2*)g_yr)[(size_t)v * 32 + lane];
    float2 b2 = make_float2(bias[2 * lane], bias[2 * lane + 1]);
    float2 o;
    o.x = acc.x * inv + yr.x + b2.x;
    o.y = acc.y * inv + yr.y + b2.y;
    if (LAYER == 1) { o.x = fmaxf(o.x, 0.f); o.y = fmaxf(o.y, 0.f); }
    float2* out = (float2*)((LAYER == 1) ? g_h : g_h2);
    out[(size_t)v * 32 + lane] = o;
}

// ---------------- edge-dot classifier ----------------
__global__ void edge_dot_kernel(const int* __restrict__ ei,
                                float* __restrict__ out, int E) {
    unsigned t = blockIdx.x * blockDim.x + threadIdx.x;
    unsigned e = t >> 3, q = t & 7;
    if (e >= (unsigned)E) return;
    int s = __ldg(ei + e);
    int d = __ldg(ei + E + e);
    const float4* hs = (const float4*)g_h2 + (size_t)s * 16;
    const float4* hd = (const float4*)g_h2 + (size_t)d * 16;
    float4 a0 = hs[2 * q], a1 = hs[2 * q + 1];
    float4 c0 = hd[2 * q], c1 = hd[2 * q + 1];
    float sum = a0.x * c0.x + a0.y * c0.y + a0.z * c0.z + a0.w * c0.w
              + a1.x * c1.x + a1.y * c1.y + a1.z * c1.z + a1.w * c1.w;
    sum += __shfl_xor_sync(0xffffffffu, sum, 1);
    sum += __shfl_xor_sync(0xffffffffu, sum, 2);
    sum += __shfl_xor_sync(0xffffffffu, sum, 4);
    if (q == 0) out[e] = sum;
}

// ---------------- launch ----------------
extern "C" void kernel_launch(void* const* d_in, const int* in_sizes, int n_in,
                              void* d_out, int out_size) {
    const float* emb = (const float*)d_in[0];
    const float* Wl1 = (const float*)d_in[1];
    const float* Wr1 = (const float*)d_in[2];
    const float* b1  = (const float*)d_in[3];
    const float* Wl2 = (const float*)d_in[4];
    const float* Wr2 = (const float*)d_in[5];
    const float* b2  = (const float*)d_in[6];
    const int*   nid = (const int*)d_in[7];
    const int*   ei  = (const int*)d_in[8];
    float* out = (float*)d_out;

    int n = in_sizes[0] / H;       // 100000
    int E = in_sizes[8] / 2;       // 1600000

    unsigned thr = 256;
    unsigned pb  = ((unsigned)n * 16 + thr - 1) / thr;
    unsigned eb  = ((unsigned)E + thr - 1) / thr;
    unsigned nb  = ((unsigned)n + thr - 1) / thr;
    unsigned gmb = ((unsigned)n + 31) / 32;
    unsigned agb = ((unsigned)n + 7) / 8;
    unsigned db  = ((unsigned)E * 8 + thr - 1) / thr;

    prep_kernel<<<pb, thr>>>((const float4*)emb, nid, n);
    deg_kernel<<<eb, thr>>>(ei, E);
    alloc_kernel<<<nb, thr>>>(n);
    csr_kernel<<<eb, thr>>>(ei, E);

    gemm_kernel<1><<<gmb, thr>>>(Wl1, Wr1, n);
    agg_kernel<1><<<agb, thr>>>(b1, n);

    gemm_kernel<2><<<gmb, thr>>>(Wl2, Wr2, n);
    agg_kernel<2><<<agb, thr>>>(b2, n);

    edge_dot_kernel<<<db, thr>>>(ei, out, E);
}

// round 4
// speedup vs baseline: 2.2320x; 1.4173x over previous
#include <cuda_runtime.h>
#include <cstdint>

#define H 64
#define NMAX 100096
#define EMAX 2000000

// ---------------- static scratch (allocation-free) ----------------
__device__ float g_x [NMAX * H];   // gathered input features
__device__ float g_yl[NMAX * H];   // x @ Wl^T   (per layer, reused)
__device__ float g_yr[NMAX * H];   // x @ Wr^T   (per layer, reused)
__device__ float g_h [NMAX * H];   // layer-1 output
__device__ float g_h2[NMAX * H];   // layer-2 output
__device__ int   g_degi[NMAX];
__device__ int   g_off [NMAX];
__device__ int   g_cur [NMAX];
__device__ float g_inv [NMAX];
__device__ int   g_csr [EMAX];
__device__ int   g_total;
__device__ float4 g_Wp[2][64 * 32];   // packed weights, both layers

// ---------------- prologue: gather x, zero degree ----------------
__global__ void prep_kernel(const float4* __restrict__ emb,
                            const int* __restrict__ nid, int n) {
    unsigned t = blockIdx.x * blockDim.x + threadIdx.x;
    unsigned i = t >> 4, q = t & 15;
    if (i < (unsigned)n) {
        int src = __ldg(nid + i);
        ((float4*)g_x)[(size_t)i * 16 + q] = emb[(size_t)src * 16 + q];
    }
    if (t < (unsigned)n) g_degi[t] = 0;
    if (t == 0) g_total = 0;
}

// one-time weight pack: g_Wp[layer][h*32+l] = (Wl[2l][h], Wl[2l+1][h], Wr[2l][h], Wr[2l+1][h])
__global__ void pack_kernel(const float* __restrict__ Wl1, const float* __restrict__ Wr1,
                            const float* __restrict__ Wl2, const float* __restrict__ Wr2) {
    int i = blockIdx.x * blockDim.x + threadIdx.x;
    if (i >= 64 * 32) return;
    int h = i >> 5, l = i & 31;
    g_Wp[0][i] = make_float4(Wl1[(2 * l) * 64 + h], Wl1[(2 * l + 1) * 64 + h],
                             Wr1[(2 * l) * 64 + h], Wr1[(2 * l + 1) * 64 + h]);
    g_Wp[1][i] = make_float4(Wl2[(2 * l) * 64 + h], Wl2[(2 * l + 1) * 64 + h],
                             Wr2[(2 * l) * 64 + h], Wr2[(2 * l + 1) * 64 + h]);
}

__global__ void deg_kernel(const int* __restrict__ ei, int E) {
    unsigned e = blockIdx.x * blockDim.x + threadIdx.x;
    if (e >= (unsigned)E) return;
    atomicAdd(&g_degi[__ldg(ei + E + e)], 1);
}

// parallel CSR offset allocation: warp shfl-scan + one global atomic per warp.
__global__ void alloc_kernel(int n) {
    int i = blockIdx.x * blockDim.x + threadIdx.x;
    int lane = threadIdx.x & 31;
    int deg = (i < n) ? g_degi[i] : 0;
    int s = deg;
#pragma unroll
    for (int d = 1; d < 32; d <<= 1) {
        int v = __shfl_up_sync(0xffffffffu, s, d);
        if (lane >= d) s += v;
    }
    int wtot = __shfl_sync(0xffffffffu, s, 31);
    int base = 0;
    if (lane == 31) base = atomicAdd(&g_total, wtot);
    base = __shfl_sync(0xffffffffu, base, 31);
    int off = base + s - deg;
    if (i < n) {
        g_off[i] = off;
        g_cur[i] = off;
        g_inv[i] = 1.0f / fmaxf((float)deg, 1.0f);
    }
}

__global__ void csr_kernel(const int* __restrict__ ei, int E) {
    unsigned e = blockIdx.x * blockDim.x + threadIdx.x;
    if (e >= (unsigned)E) return;
    int s = __ldg(ei + e);
    int d = __ldg(ei + E + e);
    int pos = atomicAdd(&g_cur[d], 1);
    g_csr[pos] = s;
}

// ---------------- dense transform: yl = x @ Wl^T, yr = x @ Wr^T -------------
// 4 nodes/warp, coalesced W tile from g_Wp, packed fp32x2 FMA pipe.
template <int LAYER>
__global__ __launch_bounds__(256) void gemm_kernel(int n) {
    __shared__ float4 Ws[64 * 32];      // 32KB weight tile
    __shared__ float2 rb[8][4][64];     // 16KB, rb[w][m][h] = (x[h], x[h]) duplicated

    const float* __restrict__ xin = (LAYER == 1) ? g_x : g_h;
    const float4* __restrict__ src = g_Wp[LAYER - 1];
    int tid = threadIdx.x;
    for (int i = tid; i < 64 * 32; i += 256) Ws[i] = src[i];   // coalesced LDG.128
    __syncthreads();

    int warp = tid >> 5, lane = tid & 31;
    int base = (blockIdx.x * 8 + warp) * 4;

#pragma unroll
    for (int m = 0; m < 4; m++) {
        int v = base + m;
        float2 xv = (v < n) ? ((const float2*)xin)[(size_t)v * 32 + lane]
                            : make_float2(0.f, 0.f);
        rb[warp][m][2 * lane]     = make_float2(xv.x, xv.x);
        rb[warp][m][2 * lane + 1] = make_float2(xv.y, xv.y);
    }
    __syncwarp();

    unsigned long long aL[4] = {0, 0, 0, 0};
    unsigned long long aR[4] = {0, 0, 0, 0};

#pragma unroll
    for (int h = 0; h < 64; h++) {
        ulonglong2 wv = ((const ulonglong2*)Ws)[h * 32 + lane];  // (Wl pair, Wr pair)
#pragma unroll
        for (int m = 0; m < 4; m++) {
            unsigned long long x2 =
                *(const unsigned long long*)&rb[warp][m][h];     // (x[h], x[h])
            asm("fma.rn.f32x2 %0, %1, %2, %0;" : "+l"(aL[m]) : "l"(x2), "l"(wv.x));
            asm("fma.rn.f32x2 %0, %1, %2, %0;" : "+l"(aR[m]) : "l"(x2), "l"(wv.y));
        }
    }

    unsigned long long* yl8 = (unsigned long long*)g_yl;
    unsigned long long* yr8 = (unsigned long long*)g_yr;
#pragma unroll
    for (int m = 0; m < 4; m++) {
        int v = base + m;
        if (v < n) {
            yl8[(size_t)v * 32 + lane] = aL[m];
            yr8[(size_t)v * 32 + lane] = aR[m];
        }
    }
}

// ---------------- aggregation epilogue: out = act(mean_j yl_j + yr_v + b) ----
template <int LAYER>
__global__ __launch_bounds__(256) void agg_kernel(const float* __restrict__ bias,
                                                  int n) {
    int tid = threadIdx.x;
    int warp = tid >> 5, lane = tid & 31;
    int v = blockIdx.x * 8 + warp;
    if (v >= n) return;

    const float2* __restrict__ yl = (const float2*)g_yl;
    int beg = g_off[v], deg = g_degi[v], end = beg + deg;

    float2 acc = make_float2(0.f, 0.f);
    int j = beg;
    while (j + 32 <= end) {
        int idx = __ldg(g_csr + j + lane);
#pragma unroll
        for (int k = 0; k < 32; k++) {
            int s = __shfl_sync(0xffffffffu, idx, k);
            float2 t = yl[(size_t)s * 32 + lane];
            acc.x += t.x; acc.y += t.y;
        }
        j += 32;
    }
    if (j < end) {
        int nb = end - j;
        int idx = __ldg(g_csr + min(j + lane, end - 1));
        // software-pipelined: issue gather k+1 before consuming gather k
        int s0 = __shfl_sync(0xffffffffu, idx, 0);
        float2 t = yl[(size_t)s0 * 32 + lane];
        for (int k = 1; k < nb; k++) {
            int s = __shfl_sync(0xffffffffu, idx, k);
            float2 tn = yl[(size_t)s * 32 + lane];
            acc.x += t.x; acc.y += t.y;
            t = tn;
        }
        acc.x += t.x; acc.y += t.y;
    }

    float inv = g_inv[v];
    float2 yr = ((const float2*)g_yr)[(size_t)v * 32 + lane];
    float2 b2 = make_float2(bias[2 * lane], bias[2 * lane + 1]);
    float2 o;
    o.x = acc.x * inv + yr.x + b2.x;
    o.y = acc.y * inv + yr.y + b2.y;
    if (LAYER == 1) { o.x = fmaxf(o.x, 0.f); o.y = fmaxf(o.y, 0.f); }
    float2* out = (float2*)((LAYER == 1) ? g_h : g_h2);
    out[(size_t)v * 32 + lane] = o;
}

// ---------------- edge-dot classifier ----------------
__global__ void edge_dot_kernel(const int* __restrict__ ei,
                                float* __restrict__ out, int E) {
    unsigned t = blockIdx.x * blockDim.x + threadIdx.x;
    unsigned e = t >> 3, q = t & 7;
    if (e >= (unsigned)E) return;
    int s = __ldg(ei + e);
    int d = __ldg(ei + E + e);
    const float4* hs = (const float4*)g_h2 + (size_t)s * 16;
    const float4* hd = (const float4*)g_h2 + (size_t)d * 16;
    float4 a0 = hs[2 * q], a1 = hs[2 * q + 1];
    float4 c0 = hd[2 * q], c1 = hd[2 * q + 1];
    float sum = a0.x * c0.x + a0.y * c0.y + a0.z * c0.z + a0.w * c0.w
              + a1.x * c1.x + a1.y * c1.y + a1.z * c1.z + a1.w * c1.w;
    sum += __shfl_xor_sync(0xffffffffu, sum, 1);
    sum += __shfl_xor_sync(0xffffffffu, sum, 2);
    sum += __shfl_xor_sync(0xffffffffu, sum, 4);
    if (q == 0) out[e] = sum;
}

// ---------------- launch ----------------
extern "C" void kernel_launch(void* const* d_in, const int* in_sizes, int n_in,
                              void* d_out, int out_size) {
    const float* emb = (const float*)d_in[0];
    const float* Wl1 = (const float*)d_in[1];
    const float* Wr1 = (const float*)d_in[2];
    const float* b1  = (const float*)d_in[3];
    const float* Wl2 = (const float*)d_in[4];
    const float* Wr2 = (const float*)d_in[5];
    const float* b2  = (const float*)d_in[6];
    const int*   nid = (const int*)d_in[7];
    const int*   ei  = (const int*)d_in[8];
    float* out = (float*)d_out;

    int n = in_sizes[0] / H;       // 100000
    int E = in_sizes[8] / 2;       // 1600000

    unsigned thr = 256;
    unsigned pb  = ((unsigned)n * 16 + thr - 1) / thr;
    unsigned eb  = ((unsigned)E + thr - 1) / thr;
    unsigned nb  = ((unsigned)n + thr - 1) / thr;
    unsigned gmb = ((unsigned)n + 31) / 32;
    unsigned agb = ((unsigned)n + 7) / 8;
    unsigned db  = ((unsigned)E * 8 + thr - 1) / thr;

    prep_kernel<<<pb, thr>>>((const float4*)emb, nid, n);
    pack_kernel<<<8, thr>>>(Wl1, Wr1, Wl2, Wr2);
    deg_kernel<<<eb, thr>>>(ei, E);
    alloc_kernel<<<nb, thr>>>(n);
    csr_kernel<<<eb, thr>>>(ei, E);

    gemm_kernel<1><<<gmb, thr>>>(n);
    agg_kernel<1><<<agb, thr>>>(b1, n);

    gemm_kernel<2><<<gmb, thr>>>(n);
    agg_kernel<2><<<agb, thr>>>(b2, n);

    edge_dot_kernel<<<db, thr>>>(ei, out, E);
}

// round 5
// speedup vs baseline: 2.4635x; 1.1037x over previous
#include <cuda_runtime.h>
#include <cstdint>

#define H 64
#define NMAX 100096
#define EMAX 2000000

// ---------------- static scratch (allocation-free) ----------------
// g_degi and g_total rely on a zero-on-exit invariant: zero-initialized at
// module load, re-zeroed by agg_kernel<2> / csr_kernel after last use, so
// every call (correctness + each replay) starts from the same state.
__device__ float g_x [NMAX * H];
__device__ float g_yl[NMAX * H];
__device__ float g_yr[NMAX * H];
__device__ float g_h [NMAX * H];
__device__ float g_h2[NMAX * H];
__device__ int   g_degi[NMAX];
__device__ int   g_off [NMAX];
__device__ int   g_cur [NMAX];
__device__ float g_inv [NMAX];
__device__ int   g_csr [EMAX];
__device__ int   g_total;
__device__ float4 g_Wp[2][64 * 32];

// ---------------- fused prologue: gather x + degree histogram + weight pack --
__global__ void fused_prep(const float4* __restrict__ emb,
                           const int* __restrict__ nid,
                           const float* __restrict__ Wl1, const float* __restrict__ Wr1,
                           const float* __restrict__ Wl2, const float* __restrict__ Wr2,
                           const int* __restrict__ ei, int n, int E) {
    unsigned t = blockIdx.x * blockDim.x + threadIdx.x;

    // embedding gather (16 threads per node)
    unsigned i = t >> 4, q = t & 15;
    if (i < (unsigned)n) {
        int src = __ldg(nid + i);
        ((float4*)g_x)[(size_t)i * 16 + q] = emb[(size_t)src * 16 + q];
    }
    // degree histogram (g_degi is zero by invariant)
    if (t < (unsigned)E) {
        atomicAdd(&g_degi[__ldg(ei + E + t)], 1);
    }
    // one-time weight pack (2048 threads)
    if (t < 64 * 32) {
        int h = t >> 5, l = t & 31;
        g_Wp[0][t] = make_float4(Wl1[(2 * l) * 64 + h], Wl1[(2 * l + 1) * 64 + h],
                                 Wr1[(2 * l) * 64 + h], Wr1[(2 * l + 1) * 64 + h]);
        g_Wp[1][t] = make_float4(Wl2[(2 * l) * 64 + h], Wl2[(2 * l + 1) * 64 + h],
                                 Wr2[(2 * l) * 64 + h], Wr2[(2 * l + 1) * 64 + h]);
    }
}

// parallel CSR offset allocation: warp shfl-scan + one global atomic per warp.
__global__ void alloc_kernel(int n) {
    int i = blockIdx.x * blockDim.x + threadIdx.x;
    int lane = threadIdx.x & 31;
    int deg = (i < n) ? g_degi[i] : 0;
    int s = deg;
#pragma unroll
    for (int d = 1; d < 32; d <<= 1) {
        int v = __shfl_up_sync(0xffffffffu, s, d);
        if (lane >= d) s += v;
    }
    int wtot = __shfl_sync(0xffffffffu, s, 31);
    int base = 0;
    if (lane == 31) base = atomicAdd(&g_total, wtot);
    base = __shfl_sync(0xffffffffu, base, 31);
    int off = base + s - deg;
    if (i < n) {
        g_off[i] = off;
        g_cur[i] = off;
        g_inv[i] = 1.0f / fmaxf((float)deg, 1.0f);
    }
}

__global__ void csr_kernel(const int* __restrict__ ei, int E) {
    unsigned e = blockIdx.x * blockDim.x + threadIdx.x;
    if (e == 0) g_total = 0;               // restore invariant (alloc is done)
    if (e >= (unsigned)E) return;
    int s = __ldg(ei + e);
    int d = __ldg(ei + E + e);
    int pos = atomicAdd(&g_cur[d], 1);
    g_csr[pos] = s;
}

// ---------------- dense transform: yl = x @ Wl^T, yr = x @ Wr^T -------------
template <int LAYER>
__global__ __launch_bounds__(256) void gemm_kernel(int n) {
    __shared__ float4 Ws[64 * 32];
    __shared__ float2 rb[8][4][64];

    const float* __restrict__ xin = (LAYER == 1) ? g_x : g_h;
    const float4* __restrict__ src = g_Wp[LAYER - 1];
    int tid = threadIdx.x;
    for (int i = tid; i < 64 * 32; i += 256) Ws[i] = src[i];
    __syncthreads();

    int warp = tid >> 5, lane = tid & 31;
    int base = (blockIdx.x * 8 + warp) * 4;

#pragma unroll
    for (int m = 0; m < 4; m++) {
        int v = base + m;
        float2 xv = (v < n) ? ((const float2*)xin)[(size_t)v * 32 + lane]
                            : make_float2(0.f, 0.f);
        rb[warp][m][2 * lane]     = make_float2(xv.x, xv.x);
        rb[warp][m][2 * lane + 1] = make_float2(xv.y, xv.y);
    }
    __syncwarp();

    unsigned long long aL[4] = {0, 0, 0, 0};
    unsigned long long aR[4] = {0, 0, 0, 0};

#pragma unroll
    for (int h = 0; h < 64; h++) {
        ulonglong2 wv = ((const ulonglong2*)Ws)[h * 32 + lane];
#pragma unroll
        for (int m = 0; m < 4; m++) {
            unsigned long long x2 =
                *(const unsigned long long*)&rb[warp][m][h];
            asm("fma.rn.f32x2 %0, %1, %2, %0;" : "+l"(aL[m]) : "l"(x2), "l"(wv.x));
            asm("fma.rn.f32x2 %0, %1, %2, %0;" : "+l"(aR[m]) : "l"(x2), "l"(wv.y));
        }
    }

    unsigned long long* yl8 = (unsigned long long*)g_yl;
    unsigned long long* yr8 = (unsigned long long*)g_yr;
#pragma unroll
    for (int m = 0; m < 4; m++) {
        int v = base + m;
        if (v < n) {
            yl8[(size_t)v * 32 + lane] = aL[m];
            yr8[(size_t)v * 32 + lane] = aR[m];
        }
    }
}

// ---------------- aggregation epilogue: out = act(mean_j yl_j + yr_v + b) ----
template <int LAYER>
__global__ __launch_bounds__(256) void agg_kernel(const float* __restrict__ bias,
                                                  int n) {
    int tid = threadIdx.x;
    int warp = tid >> 5, lane = tid & 31;
    int v = blockIdx.x * 8 + warp;
    if (v >= n) return;

    const unsigned long long* __restrict__ yl8 = (const unsigned long long*)g_yl;
    int beg = g_off[v], deg = g_degi[v], end = beg + deg;

    unsigned long long acc = 0;   // packed f32x2 accumulator
    int j = beg;
    while (j + 32 <= end) {
        int idx = __ldg(g_csr + j + lane);
#pragma unroll
        for (int k = 0; k < 32; k++) {
            int s = __shfl_sync(0xffffffffu, idx, k);
            unsigned long long t = yl8[(size_t)s * 32 + lane];
            asm("add.rn.f32x2 %0, %0, %1;" : "+l"(acc) : "l"(t));
        }
        j += 32;
    }
    if (j < end) {
        int nb = end - j;
        int idx = __ldg(g_csr + min(j + lane, end - 1));
        int s0 = __shfl_sync(0xffffffffu, idx, 0);
        unsigned long long t = yl8[(size_t)s0 * 32 + lane];
        for (int k = 1; k < nb; k++) {
            int s = __shfl_sync(0xffffffffu, idx, k);
            unsigned long long tn = yl8[(size_t)s * 32 + lane];
            asm("add.rn.f32x2 %0, %0, %1;" : "+l"(acc) : "l"(t));
            t = tn;
        }
        asm("add.rn.f32x2 %0, %0, %1;" : "+l"(acc) : "l"(t));
    }

    float2 accf = *(float2*)&acc;
    float inv = g_inv[v];
    float2 yr = ((const float2*)g_yr)[(size_t)v * 32 + lane];
    float2 b2 = make_float2(bias[2 * lane], bias[2 * lane + 1]);
    float2 o;
    o.x = accf.x * inv + yr.x + b2.x;
    o.y = accf.y * inv + yr.y + b2.y;
    if (LAYER == 1) { o.x = fmaxf(o.x, 0.f); o.y = fmaxf(o.y, 0.f); }
    float2* out = (float2*)((LAYER == 1) ? g_h : g_h2);
    out[(size_t)v * 32 + lane] = o;

    if (LAYER == 2 && lane == 0) g_degi[v] = 0;   // restore invariant
}

// ---------------- edge-dot classifier ----------------
__global__ void edge_dot_kernel(const int* __restrict__ ei,
                                float* __restrict__ out, int E) {
    unsigned t = blockIdx.x * blockDim.x + threadIdx.x;
    unsigned e = t >> 3, q = t & 7;
    if (e >= (unsigned)E) return;
    int s = __ldg(ei + e);
    int d = __ldg(ei + E + e);
    const float4* hs = (const float4*)g_h2 + (size_t)s * 16;
    const float4* hd = (const float4*)g_h2 + (size_t)d * 16;
    float4 a0 = hs[2 * q], a1 = hs[2 * q + 1];
    float4 c0 = hd[2 * q], c1 = hd[2 * q + 1];
    float sum = a0.x * c0.x + a0.y * c0.y + a0.z * c0.z + a0.w * c0.w
              + a1.x * c1.x + a1.y * c1.y + a1.z * c1.z + a1.w * c1.w;
    sum += __shfl_xor_sync(0xffffffffu, sum, 1);
    sum += __shfl_xor_sync(0xffffffffu, sum, 2);
    sum += __shfl_xor_sync(0xffffffffu, sum, 4);
    if (q == 0) out[e] = sum;
}

// ---------------- launch ----------------
extern "C" void kernel_launch(void* const* d_in, const int* in_sizes, int n_in,
                              void* d_out, int out_size) {
    const float* emb = (const float*)d_in[0];
    const float* Wl1 = (const float*)d_in[1];
    const float* Wr1 = (const float*)d_in[2];
    const float* b1  = (const float*)d_in[3];
    const float* Wl2 = (const float*)d_in[4];
    const float* Wr2 = (const float*)d_in[5];
    const float* b2  = (const float*)d_in[6];
    const int*   nid = (const int*)d_in[7];
    const int*   ei  = (const int*)d_in[8];
    float* out = (float*)d_out;

    int n = in_sizes[0] / H;       // 100000
    int E = in_sizes[8] / 2;       // 1600000

    // persistent side stream + events for captured fork (host objects only,
    // created once; no device memory involved)
    static cudaStream_t sB = nullptr;
    static cudaEvent_t evF = nullptr, evJ = nullptr;
    if (!sB) {
        cudaStreamCreateWithFlags(&sB, cudaStreamNonBlocking);
        cudaEventCreateWithFlags(&evF, cudaEventDisableTiming);
        cudaEventCreateWithFlags(&evJ, cudaEventDisableTiming);
    }

    unsigned thr = 256;
    unsigned fb  = ((unsigned)(E > n * 16 ? E : n * 16) + thr - 1) / thr;
    unsigned eb  = ((unsigned)E + thr - 1) / thr;
    unsigned nb  = ((unsigned)n + thr - 1) / thr;
    unsigned gmb = ((unsigned)n + 31) / 32;
    unsigned agb = ((unsigned)n + 7) / 8;
    unsigned db  = ((unsigned)E * 8 + thr - 1) / thr;

    fused_prep<<<fb, thr>>>((const float4*)emb, nid, Wl1, Wr1, Wl2, Wr2, ei, n, E);

    // fork: CSR build on sB, gemm1 on main stream, join before agg1
    cudaEventRecord(evF, 0);
    cudaStreamWaitEvent(sB, evF, 0);
    alloc_kernel<<<nb, thr, 0, sB>>>(n);
    csr_kernel<<<eb, thr, 0, sB>>>(ei, E);
    cudaEventRecord(evJ, sB);

    gemm_kernel<1><<<gmb, thr>>>(n);
    cudaStreamWaitEvent(0, evJ, 0);

    agg_kernel<1><<<agb, thr>>>(b1, n);
    gemm_kernel<2><<<gmb, thr>>>(n);
    agg_kernel<2><<<agb, thr>>>(b2, n);
    edge_dot_kernel<<<db, thr>>>(ei, out, E);
}

// round 6
// speedup vs baseline: 2.6691x; 1.0835x over previous
#include <cuda_runtime.h>
#include <cstdint>

#define H 64
#define NMAX 100096
#define EMAX 2000000

// ---------------- static scratch (allocation-free) ----------------
// g_degi and g_total rely on a zero-on-exit invariant: zero-initialized at
// module load, re-zeroed by agg_kernel<2> / csr_kernel after last use, so
// every call (correctness + each replay) starts from the same state.
__device__ float g_x [NMAX * H];
__device__ float g_yl[NMAX * H];
__device__ float g_yr[NMAX * H];
__device__ float g_h [NMAX * H];
__device__ float g_h2[NMAX * H];
__device__ int   g_degi[NMAX];
__device__ int   g_off [NMAX];
__device__ int   g_cur [NMAX];
__device__ float g_inv [NMAX];
__device__ int   g_csr [EMAX];
__device__ int   g_total;
__device__ float4 g_Wp[2][64 * 32];

// ---------------- fused prologue: gather x + degree histogram + weight pack --
__global__ void fused_prep(const float4* __restrict__ emb,
                           const int* __restrict__ nid,
                           const float* __restrict__ Wl1, const float* __restrict__ Wr1,
                           const float* __restrict__ Wl2, const float* __restrict__ Wr2,
                           const int* __restrict__ ei, int n, int E) {
    unsigned t = blockIdx.x * blockDim.x + threadIdx.x;

    unsigned i = t >> 4, q = t & 15;
    if (i < (unsigned)n) {
        int src = __ldg(nid + i);
        ((float4*)g_x)[(size_t)i * 16 + q] = emb[(size_t)src * 16 + q];
    }
    if (t < (unsigned)E) {
        atomicAdd(&g_degi[__ldg(ei + E + t)], 1);
    }
    if (t < 64 * 32) {
        int h = t >> 5, l = t & 31;
        g_Wp[0][t] = make_float4(Wl1[(2 * l) * 64 + h], Wl1[(2 * l + 1) * 64 + h],
                                 Wr1[(2 * l) * 64 + h], Wr1[(2 * l + 1) * 64 + h]);
        g_Wp[1][t] = make_float4(Wl2[(2 * l) * 64 + h], Wl2[(2 * l + 1) * 64 + h],
                                 Wr2[(2 * l) * 64 + h], Wr2[(2 * l + 1) * 64 + h]);
    }
}

// parallel CSR offset allocation: warp shfl-scan + one global atomic per warp.
__global__ void alloc_kernel(int n) {
    int i = blockIdx.x * blockDim.x + threadIdx.x;
    int lane = threadIdx.x & 31;
    int deg = (i < n) ? g_degi[i] : 0;
    int s = deg;
#pragma unroll
    for (int d = 1; d < 32; d <<= 1) {
        int v = __shfl_up_sync(0xffffffffu, s, d);
        if (lane >= d) s += v;
    }
    int wtot = __shfl_sync(0xffffffffu, s, 31);
    int base = 0;
    if (lane == 31) base = atomicAdd(&g_total, wtot);
    base = __shfl_sync(0xffffffffu, base, 31);
    int off = base + s - deg;
    if (i < n) {
        g_off[i] = off;
        g_cur[i] = off;
        g_inv[i] = 1.0f / fmaxf((float)deg, 1.0f);
    }
}

__global__ void csr_kernel(const int* __restrict__ ei, int E) {
    unsigned e = blockIdx.x * blockDim.x + threadIdx.x;
    if (e == 0) g_total = 0;               // restore invariant (alloc is done)
    if (e >= (unsigned)E) return;
    int s = __ldg(ei + e);
    int d = __ldg(ei + E + e);
    int pos = atomicAdd(&g_cur[d], 1);
    g_csr[pos] = s;
}

// ---------------- dense transform: yl = x @ Wl^T, yr = x @ Wr^T -------------
// 8 nodes/warp, 128 threads/block, paired-x LDS.128 broadcasts.
// Per warp per h: 4 weight wavefronts + 2 x wavefronts vs 16 FFMA2.
template <int LAYER>
__global__ __launch_bounds__(128) void gemm_kernel(int n) {
    __shared__ float4 Ws[64 * 32];          // 32KB weight tile
    __shared__ float4 rb[4][8][32];         // 16KB: rb[w][m][l] = (x[2l],x[2l],x[2l+1],x[2l+1])

    const float* __restrict__ xin = (LAYER == 1) ? g_x : g_h;
    const float4* __restrict__ src = g_Wp[LAYER - 1];
    int tid = threadIdx.x;
#pragma unroll
    for (int i = 0; i < 16; i++) Ws[tid + 128 * i] = src[tid + 128 * i];
    __syncthreads();

    int warp = tid >> 5, lane = tid & 31;
    int base = (blockIdx.x * 4 + warp) * 8;

#pragma unroll
    for (int m = 0; m < 8; m++) {
        int v = base + m;
        float2 xv = (v < n) ? ((const float2*)xin)[(size_t)v * 32 + lane]
                            : make_float2(0.f, 0.f);
        rb[warp][m][lane] = make_float4(xv.x, xv.x, xv.y, xv.y);   // STS.128, conflict-free
    }
    __syncwarp();

    unsigned long long aL[8], aR[8];
#pragma unroll
    for (int m = 0; m < 8; m++) { aL[m] = 0ull; aR[m] = 0ull; }

    const ulonglong2* __restrict__ Wv = (const ulonglong2*)Ws;
#pragma unroll 8
    for (int p = 0; p < 32; p++) {         // p = h/2
        ulonglong2 wv0 = Wv[(2 * p) * 32 + lane];       // h=2p:   (Wl pair, Wr pair)
        ulonglong2 wv1 = Wv[(2 * p + 1) * 32 + lane];   // h=2p+1
#pragma unroll
        for (int m = 0; m < 8; m++) {
            ulonglong2 xp = ((const ulonglong2*)rb[warp][m])[p];   // broadcast LDS.128
            asm("fma.rn.f32x2 %0, %1, %2, %0;" : "+l"(aL[m]) : "l"(xp.x), "l"(wv0.x));
            asm("fma.rn.f32x2 %0, %1, %2, %0;" : "+l"(aR[m]) : "l"(xp.x), "l"(wv0.y));
            asm("fma.rn.f32x2 %0, %1, %2, %0;" : "+l"(aL[m]) : "l"(xp.y), "l"(wv1.x));
            asm("fma.rn.f32x2 %0, %1, %2, %0;" : "+l"(aR[m]) : "l"(xp.y), "l"(wv1.y));
        }
    }

    unsigned long long* yl8 = (unsigned long long*)g_yl;
    unsigned long long* yr8 = (unsigned long long*)g_yr;
#pragma unroll
    for (int m = 0; m < 8; m++) {
        int v = base + m;
        if (v < n) {
            yl8[(size_t)v * 32 + lane] = aL[m];
            yr8[(size_t)v * 32 + lane] = aR[m];
        }
    }
}

// ---------------- aggregation epilogue: out = act(mean_j yl_j + yr_v + b) ----
template <int LAYER>
__global__ __launch_bounds__(256) void agg_kernel(const float* __restrict__ bias,
                                                  int n) {
    int tid = threadIdx.x;
    int warp = tid >> 5, lane = tid & 31;
    int v = blockIdx.x * 8 + warp;
    if (v >= n) return;

    const unsigned long long* __restrict__ yl8 = (const unsigned long long*)g_yl;
    int beg = g_off[v], deg = g_degi[v], end = beg + deg;

    unsigned long long acc = 0;
    int j = beg;
    while (j + 32 <= end) {
        int idx = __ldg(g_csr + j + lane);
#pragma unroll
        for (int k = 0; k < 32; k++) {
            int s = __shfl_sync(0xffffffffu, idx, k);
            unsigned long long t = yl8[(size_t)s * 32 + lane];
            asm("add.rn.f32x2 %0, %0, %1;" : "+l"(acc) : "l"(t));
        }
        j += 32;
    }
    if (j < end) {
        int nb = end - j;
        int idx = __ldg(g_csr + min(j + lane, end - 1));
        int s0 = __shfl_sync(0xffffffffu, idx, 0);
        unsigned long long t = yl8[(size_t)s0 * 32 + lane];
        for (int k = 1; k < nb; k++) {
            int s = __shfl_sync(0xffffffffu, idx, k);
            unsigned long long tn = yl8[(size_t)s * 32 + lane];
            asm("add.rn.f32x2 %0, %0, %1;" : "+l"(acc) : "l"(t));
            t = tn;
        }
        asm("add.rn.f32x2 %0, %0, %1;" : "+l"(acc) : "l"(t));
    }

    float2 accf = *(float2*)&acc;
    float inv = g_inv[v];
    float2 yr = ((const float2*)g_yr)[(size_t)v * 32 + lane];
    float2 b2 = make_float2(bias[2 * lane], bias[2 * lane + 1]);
    float2 o;
    o.x = accf.x * inv + yr.x + b2.x;
    o.y = accf.y * inv + yr.y + b2.y;
    if (LAYER == 1) { o.x = fmaxf(o.x, 0.f); o.y = fmaxf(o.y, 0.f); }
    float2* out = (float2*)((LAYER == 1) ? g_h : g_h2);
    out[(size_t)v * 32 + lane] = o;

    if (LAYER == 2 && lane == 0) g_degi[v] = 0;   // restore invariant
}

// ---------------- edge-dot classifier ----------------
__global__ void edge_dot_kernel(const int* __restrict__ ei,
                                float* __restrict__ out, int E) {
    unsigned t = blockIdx.x * blockDim.x + threadIdx.x;
    unsigned e = t >> 3, q = t & 7;
    if (e >= (unsigned)E) return;
    int s = __ldg(ei + e);
    int d = __ldg(ei + E + e);
    const float4* hs = (const float4*)g_h2 + (size_t)s * 16;
    const float4* hd = (const float4*)g_h2 + (size_t)d * 16;
    float4 a0 = hs[2 * q], a1 = hs[2 * q + 1];
    float4 c0 = hd[2 * q], c1 = hd[2 * q + 1];
    float sum = a0.x * c0.x + a0.y * c0.y + a0.z * c0.z + a0.w * c0.w
              + a1.x * c1.x + a1.y * c1.y + a1.z * c1.z + a1.w * c1.w;
    sum += __shfl_xor_sync(0xffffffffu, sum, 1);
    sum += __shfl_xor_sync(0xffffffffu, sum, 2);
    sum += __shfl_xor_sync(0xffffffffu, sum, 4);
    if (q == 0) out[e] = sum;
}

// ---------------- launch ----------------
extern "C" void kernel_launch(void* const* d_in, const int* in_sizes, int n_in,
                              void* d_out, int out_size) {
    const float* emb = (const float*)d_in[0];
    const float* Wl1 = (const float*)d_in[1];
    const float* Wr1 = (const float*)d_in[2];
    const float* b1  = (const float*)d_in[3];
    const float* Wl2 = (const float*)d_in[4];
    const float* Wr2 = (const float*)d_in[5];
    const float* b2  = (const float*)d_in[6];
    const int*   nid = (const int*)d_in[7];
    const int*   ei  = (const int*)d_in[8];
    float* out = (float*)d_out;

    int n = in_sizes[0] / H;       // 100000
    int E = in_sizes[8] / 2;       // 1600000

    static cudaStream_t sB = nullptr;
    static cudaEvent_t evF = nullptr, evJ = nullptr;
    if (!sB) {
        cudaStreamCreateWithFlags(&sB, cudaStreamNonBlocking);
        cudaEventCreateWithFlags(&evF, cudaEventDisableTiming);
        cudaEventCreateWithFlags(&evJ, cudaEventDisableTiming);
    }

    unsigned thr = 256;
    unsigned fb  = ((unsigned)(E > n * 16 ? E : n * 16) + thr - 1) / thr;
    unsigned eb  = ((unsigned)E + thr - 1) / thr;
    unsigned nb  = ((unsigned)n + thr - 1) / thr;
    unsigned gmb = ((unsigned)n + 31) / 32;          // 8 nodes/warp, 4 warps/block
    unsigned agb = ((unsigned)n + 7) / 8;
    unsigned db  = ((unsigned)E * 8 + thr - 1) / thr;

    fused_prep<<<fb, thr>>>((const float4*)emb, nid, Wl1, Wr1, Wl2, Wr2, ei, n, E);

    // fork: CSR build on sB, gemm1 on main stream, join before agg1
    cudaEventRecord(evF, 0);
    cudaStreamWaitEvent(sB, evF, 0);
    alloc_kernel<<<nb, thr, 0, sB>>>(n);
    csr_kernel<<<eb, thr, 0, sB>>>(ei, E);
    cudaEventRecord(evJ, sB);

    gemm_kernel<1><<<gmb, 128>>>(n);
    cudaStreamWaitEvent(0, evJ, 0);

    agg_kernel<1><<<agb, thr>>>(b1, n);
    gemm_kernel<2><<<gmb, 128>>>(n);
    agg_kernel<2><<<agb, thr>>>(b2, n);
    edge_dot_kernel<<<db, thr>>>(ei, out, E);
}

// round 7
// speedup vs baseline: 2.9507x; 1.1055x over previous
#include <cuda_runtime.h>
#include <cuda_fp16.h>
#include <cstdint>

#define H 64
#define NMAX 100096
#define EMAX 2000000

// ---------------- static scratch (allocation-free) ----------------
// g_degi / g_total use a zero-on-exit invariant (zeroed at load, re-zeroed
// after last use each call) so every replay starts from identical state.
__device__ float  g_x [NMAX * H];
__device__ __half g_ylh[NMAX * H];    // x @ Wl^T, fp16 (gather-read by agg)
__device__ float  g_yr[NMAX * H];     // x @ Wr^T, fp32
__device__ float  g_h [NMAX * H];     // layer-1 output (fp32, feeds gemm2)
__device__ __half g_h2h[NMAX * H];    // layer-2 output (fp16, feeds edge dot)
__device__ int    g_degi[NMAX];
__device__ int    g_off [NMAX];
__device__ int    g_cur [NMAX];
__device__ float  g_inv [NMAX];
__device__ int    g_csr [EMAX];
__device__ int    g_total;
__device__ float4 g_Wp[2][64 * 32];

// ---------------- fused prologue: gather x + degree histogram + weight pack --
__global__ void fused_prep(const float4* __restrict__ emb,
                           const int* __restrict__ nid,
                           const float* __restrict__ Wl1, const float* __restrict__ Wr1,
                           const float* __restrict__ Wl2, const float* __restrict__ Wr2,
                           const int* __restrict__ ei, int n, int E) {
    unsigned t = blockIdx.x * blockDim.x + threadIdx.x;

    unsigned i = t >> 4, q = t & 15;
    if (i < (unsigned)n) {
        int src = __ldg(nid + i);
        ((float4*)g_x)[(size_t)i * 16 + q] = emb[(size_t)src * 16 + q];
    }
    if (t < (unsigned)E) {
        atomicAdd(&g_degi[__ldg(ei + E + t)], 1);
    }
    if (t < 64 * 32) {
        int h = t >> 5, l = t & 31;
        g_Wp[0][t] = make_float4(Wl1[(2 * l) * 64 + h], Wl1[(2 * l + 1) * 64 + h],
                                 Wr1[(2 * l) * 64 + h], Wr1[(2 * l + 1) * 64 + h]);
        g_Wp[1][t] = make_float4(Wl2[(2 * l) * 64 + h], Wl2[(2 * l + 1) * 64 + h],
                                 Wr2[(2 * l) * 64 + h], Wr2[(2 * l + 1) * 64 + h]);
    }
}

// parallel CSR offset allocation: warp shfl-scan + one global atomic per warp.
__global__ void alloc_kernel(int n) {
    int i = blockIdx.x * blockDim.x + threadIdx.x;
    int lane = threadIdx.x & 31;
    int deg = (i < n) ? g_degi[i] : 0;
    int s = deg;
#pragma unroll
    for (int d = 1; d < 32; d <<= 1) {
        int v = __shfl_up_sync(0xffffffffu, s, d);
        if (lane >= d) s += v;
    }
    int wtot = __shfl_sync(0xffffffffu, s, 31);
    int base = 0;
    if (lane == 31) base = atomicAdd(&g_total, wtot);
    base = __shfl_sync(0xffffffffu, base, 31);
    int off = base + s - deg;
    if (i < n) {
        g_off[i] = off;
        g_cur[i] = off;
        g_inv[i] = 1.0f / fmaxf((float)deg, 1.0f);
    }
}

__global__ void csr_kernel(const int* __restrict__ ei, int E) {
    unsigned e = blockIdx.x * blockDim.x + threadIdx.x;
    if (e == 0) g_total = 0;               // restore invariant
    if (e >= (unsigned)E) return;
    int s = __ldg(ei + e);
    int d = __ldg(ei + E + e);
    int pos = atomicAdd(&g_cur[d], 1);
    g_csr[pos] = s;
}

// ---------------- dense transform: yl = x @ Wl^T (fp16), yr = x @ Wr^T ------
// 16 nodes/warp: per p (=2 h-cols) 24 smem wavefronts vs 64 FFMA2 -> fma-bound.
template <int LAYER>
__global__ __launch_bounds__(128) void gemm_kernel(int n) {
    __shared__ float4 Ws[64 * 32];          // 32KB weight tile
    __shared__ float4 rb[4][16][32];        // 32KB: rb[w][m][l]=(x[2l],x[2l],x[2l+1],x[2l+1])

    const float* __restrict__ xin = (LAYER == 1) ? g_x : g_h;
    const float4* __restrict__ src = g_Wp[LAYER - 1];
    int tid = threadIdx.x;
#pragma unroll
    for (int i = 0; i < 16; i++) Ws[tid + 128 * i] = src[tid + 128 * i];
    __syncthreads();

    int warp = tid >> 5, lane = tid & 31;
    int base = (blockIdx.x * 4 + warp) * 16;

#pragma unroll
    for (int m = 0; m < 16; m++) {
        int v = base + m;
        float2 xv = (v < n) ? ((const float2*)xin)[(size_t)v * 32 + lane]
                            : make_float2(0.f, 0.f);
        rb[warp][m][lane] = make_float4(xv.x, xv.x, xv.y, xv.y);
    }
    __syncwarp();

    unsigned long long aL[16], aR[16];
#pragma unroll
    for (int m = 0; m < 16; m++) { aL[m] = 0ull; aR[m] = 0ull; }

    const ulonglong2* __restrict__ Wv = (const ulonglong2*)Ws;
#pragma unroll 4
    for (int p = 0; p < 32; p++) {
        ulonglong2 wv0 = Wv[(2 * p) * 32 + lane];
        ulonglong2 wv1 = Wv[(2 * p + 1) * 32 + lane];
#pragma unroll
        for (int m = 0; m < 16; m++) {
            ulonglong2 xp = ((const ulonglong2*)rb[warp][m])[p];
            asm("fma.rn.f32x2 %0, %1, %2, %0;" : "+l"(aL[m]) : "l"(xp.x), "l"(wv0.x));
            asm("fma.rn.f32x2 %0, %1, %2, %0;" : "+l"(aR[m]) : "l"(xp.x), "l"(wv0.y));
            asm("fma.rn.f32x2 %0, %1, %2, %0;" : "+l"(aL[m]) : "l"(xp.y), "l"(wv1.x));
            asm("fma.rn.f32x2 %0, %1, %2, %0;" : "+l"(aR[m]) : "l"(xp.y), "l"(wv1.y));
        }
    }

    __half2* ylh2 = (__half2*)g_ylh;
    unsigned long long* yr8 = (unsigned long long*)g_yr;
#pragma unroll
    for (int m = 0; m < 16; m++) {
        int v = base + m;
        if (v < n) {
            float2 fl = *(float2*)&aL[m];
            ylh2[(size_t)v * 32 + lane] = __floats2half2_rn(fl.x, fl.y);
            yr8[(size_t)v * 32 + lane] = aR[m];
        }
    }
}

// ---------------- aggregation epilogue: out = act(mean_j yl_j + yr_v + b) ----
// yl gathered as half2 (halves L2 traffic), accumulated in fp32.
template <int LAYER>
__global__ __launch_bounds__(256) void agg_kernel(const float* __restrict__ bias,
                                                  int n) {
    int tid = threadIdx.x;
    int warp = tid >> 5, lane = tid & 31;
    int v = blockIdx.x * 8 + warp;
    if (v >= n) return;

    const __half2* __restrict__ yl2 = (const __half2*)g_ylh;
    int beg = g_off[v], deg = g_degi[v], end = beg + deg;

    float2 acc = make_float2(0.f, 0.f);
    int j = beg;
    while (j + 32 <= end) {
        int idx = __ldg(g_csr + j + lane);
#pragma unroll
        for (int k = 0; k < 32; k++) {
            int s = __shfl_sync(0xffffffffu, idx, k);
            float2 t = __half22float2(yl2[(size_t)s * 32 + lane]);
            acc.x += t.x; acc.y += t.y;
        }
        j += 32;
    }
    if (j < end) {
        int nb = end - j;
        int idx = __ldg(g_csr + min(j + lane, end - 1));
        int s0 = __shfl_sync(0xffffffffu, idx, 0);
        __half2 t = yl2[(size_t)s0 * 32 + lane];
        for (int k = 1; k < nb; k++) {
            int s = __shfl_sync(0xffffffffu, idx, k);
            __half2 tn = yl2[(size_t)s * 32 + lane];
            float2 tf = __half22float2(t);
            acc.x += tf.x; acc.y += tf.y;
            t = tn;
        }
        float2 tf = __half22float2(t);
        acc.x += tf.x; acc.y += tf.y;
    }

    float inv = g_inv[v];
    float2 yr = ((const float2*)g_yr)[(size_t)v * 32 + lane];
    float2 b2 = make_float2(bias[2 * lane], bias[2 * lane + 1]);
    float2 o;
    o.x = acc.x * inv + yr.x + b2.x;
    o.y = acc.y * inv + yr.y + b2.y;
    if (LAYER == 1) {
        o.x = fmaxf(o.x, 0.f); o.y = fmaxf(o.y, 0.f);
        ((float2*)g_h)[(size_t)v * 32 + lane] = o;
    } else {
        ((__half2*)g_h2h)[(size_t)v * 32 + lane] = __floats2half2_rn(o.x, o.y);
        if (lane == 0) g_degi[v] = 0;     // restore invariant
    }
}

// ---------------- edge-dot classifier (fp16 inputs, fp32 accumulate) --------
__global__ void edge_dot_kernel(const int* __restrict__ ei,
                                float* __restrict__ out, int E) {
    unsigned t = blockIdx.x * blockDim.x + threadIdx.x;
    unsigned e = t >> 3, q = t & 7;
    if (e >= (unsigned)E) return;
    int s = __ldg(ei + e);
    int d = __ldg(ei + E + e);
    const uint4* hs = (const uint4*)(g_h2h + (size_t)s * 64);
    const uint4* hd = (const uint4*)(g_h2h + (size_t)d * 64);
    uint4 ua = hs[q];           // 8 halves
    uint4 ub = hd[q];
    float2 a0 = __half22float2(*(__half2*)&ua.x), b0 = __half22float2(*(__half2*)&ub.x);
    float2 a1 = __half22float2(*(__half2*)&ua.y), b1 = __half22float2(*(__half2*)&ub.y);
    float2 a2 = __half22float2(*(__half2*)&ua.z), b2 = __half22float2(*(__half2*)&ub.z);
    float2 a3 = __half22float2(*(__half2*)&ua.w), b3 = __half22float2(*(__half2*)&ub.w);
    float sum = a0.x * b0.x + a0.y * b0.y + a1.x * b1.x + a1.y * b1.y
              + a2.x * b2.x + a2.y * b2.y + a3.x * b3.x + a3.y * b3.y;
    sum += __shfl_xor_sync(0xffffffffu, sum, 1);
    sum += __shfl_xor_sync(0xffffffffu, sum, 2);
    sum += __shfl_xor_sync(0xffffffffu, sum, 4);
    if (q == 0) out[e] = sum;
}

// ---------------- launch ----------------
extern "C" void kernel_launch(void* const* d_in, const int* in_sizes, int n_in,
                              void* d_out, int out_size) {
    const float* emb = (const float*)d_in[0];
    const float* Wl1 = (const float*)d_in[1];
    const float* Wr1 = (const float*)d_in[2];
    const float* b1  = (const float*)d_in[3];
    const float* Wl2 = (const float*)d_in[4];
    const float* Wr2 = (const float*)d_in[5];
    const float* b2  = (const float*)d_in[6];
    const int*   nid = (const int*)d_in[7];
    const int*   ei  = (const int*)d_in[8];
    float* out = (float*)d_out;

    int n = in_sizes[0] / H;       // 100000
    int E = in_sizes[8] / 2;       // 1600000

    static cudaStream_t sB = nullptr;
    static cudaEvent_t evF = nullptr, evJ = nullptr;
    if (!sB) {
        cudaStreamCreateWithFlags(&sB, cudaStreamNonBlocking);
        cudaEventCreateWithFlags(&evF, cudaEventDisableTiming);
        cudaEventCreateWithFlags(&evJ, cudaEventDisableTiming);
    }

    unsigned thr = 256;
    unsigned fb  = ((unsigned)(E > n * 16 ? E : n * 16) + thr - 1) / thr;
    unsigned eb  = ((unsigned)E + thr - 1) / thr;
    unsigned nb  = ((unsigned)n + thr - 1) / thr;
    unsigned gmb = ((unsigned)n + 63) / 64;          // 16 nodes/warp, 4 warps/block
    unsigned agb = ((unsigned)n + 7) / 8;
    unsigned db  = ((unsigned)E * 8 + thr - 1) / thr;

    fused_prep<<<fb, thr>>>((const float4*)emb, nid, Wl1, Wr1, Wl2, Wr2, ei, n, E);

    // fork: CSR build on sB, gemm1 on main stream, join before agg1
    cudaEventRecord(evF, 0);
    cudaStreamWaitEvent(sB, evF, 0);
    alloc_kernel<<<nb, thr, 0, sB>>>(n);
    csr_kernel<<<eb, thr, 0, sB>>>(ei, E);
    cudaEventRecord(evJ, sB);

    gemm_kernel<1><<<gmb, 128>>>(n);
    cudaStreamWaitEvent(0, evJ, 0);

    agg_kernel<1><<<agb, thr>>>(b1, n);
    gemm_kernel<2><<<gmb, 128>>>(n);
    agg_kernel<2><<<agb, thr>>>(b2, n);
    edge_dot_kernel<<<db, thr>>>(ei, out, E);
}

// round 8
// speedup vs baseline: 3.6257x; 1.2287x over previous
#include <cuda_runtime.h>
#include <cuda_fp16.h>
#include <cstdint>

#define H 64
#define NMAX 100096
#define EMAX 2000000

// ---------------- static scratch (allocation-free) ----------------
// g_degi / g_total use a zero-on-exit invariant (zeroed at load, re-zeroed
// after last use each call) so every replay starts from identical state.
__device__ __half g_xh [NMAX * H];    // gathered input features, fp16
__device__ __half g_ylh[NMAX * H];    // x @ Wl^T, fp16 (gather-read by agg)
__device__ float  g_yr[NMAX * H];     // x @ Wr^T, fp32
__device__ __half g_hh [NMAX * H];    // layer-1 output, fp16 (feeds gemm2)
__device__ __half g_h2h[NMAX * H];    // layer-2 output, fp16 (feeds edge dot)
__device__ int    g_degi[NMAX];
__device__ int    g_off [NMAX];
__device__ int    g_cur [NMAX];
__device__ float  g_inv [NMAX];
__device__ int    g_csr [EMAX];
__device__ int    g_total;
// B fragments for mma.m16n8k16: [layer][j-tile*4+k-tile][lane] -> {b0,b1}
// j-tile 0..7 = Wl rows, 8..15 = Wr rows. W = concat(Wl,Wr) [128 x 64].
__device__ uint2  g_Wfrag[2][16 * 4 * 32];

// ---------------- fused prologue: gather x(fp16) + degree + W-fragment pack --
__global__ void fused_prep(const float4* __restrict__ emb,
                           const int* __restrict__ nid,
                           const float* __restrict__ Wl1, const float* __restrict__ Wr1,
                           const float* __restrict__ Wl2, const float* __restrict__ Wr2,
                           const int* __restrict__ ei, int n, int E) {
    unsigned t = blockIdx.x * blockDim.x + threadIdx.x;

    unsigned i = t >> 4, q = t & 15;
    if (i < (unsigned)n) {
        int src = __ldg(nid + i);
        float4 f = emb[(size_t)src * 16 + q];
        __half2 h0 = __floats2half2_rn(f.x, f.y);
        __half2 h1 = __floats2half2_rn(f.z, f.w);
        ((uint2*)g_xh)[(size_t)i * 16 + q] =
            make_uint2(*(unsigned*)&h0, *(unsigned*)&h1);
    }
    if (t < (unsigned)E) {
        atomicAdd(&g_degi[__ldg(ei + E + t)], 1);
    }
    // W fragment pack: 2 layers x 16 j-tiles x 4 k-tiles x 32 lanes
    if (t < 4096) {
        int L    = t >> 11;
        int idx  = t & 2047;
        int j    = idx >> 7;          // j-tile (8 output rows)
        int tk   = (idx >> 5) & 3;    // k-tile (16 k)
        int lane = idx & 31;
        int nrow = j * 8 + (lane >> 2);
        int k0   = tk * 16 + (lane & 3) * 2;
        const float* Wl = L ? Wl2 : Wl1;
        const float* Wr = L ? Wr2 : Wr1;
        const float* Wm = (nrow < 64) ? Wl : Wr;
        int rr = nrow & 63;
        __half2 lo = __floats2half2_rn(Wm[rr * 64 + k0],     Wm[rr * 64 + k0 + 1]);
        __half2 hi = __floats2half2_rn(Wm[rr * 64 + k0 + 8], Wm[rr * 64 + k0 + 9]);
        g_Wfrag[L][(j * 4 + tk) * 32 + lane] =
            make_uint2(*(unsigned*)&lo, *(unsigned*)&hi);
    }
}

// parallel CSR offset allocation: warp shfl-scan + one global atomic per warp.
__global__ void alloc_kernel(int n) {
    int i = blockIdx.x * blockDim.x + threadIdx.x;
    int lane = threadIdx.x & 31;
    int deg = (i < n) ? g_degi[i] : 0;
    int s = deg;
#pragma unroll
    for (int d = 1; d < 32; d <<= 1) {
        int v = __shfl_up_sync(0xffffffffu, s, d);
        if (lane >= d) s += v;
    }
    int wtot = __shfl_sync(0xffffffffu, s, 31);
    int base = 0;
    if (lane == 31) base = atomicAdd(&g_total, wtot);
    base = __shfl_sync(0xffffffffu, base, 31);
    int off = base + s - deg;
    if (i < n) {
        g_off[i] = off;
        g_cur[i] = off;
        g_inv[i] = 1.0f / fmaxf((float)deg, 1.0f);
    }
}

__global__ void csr_kernel(const int* __restrict__ ei, int E) {
    unsigned e = blockIdx.x * blockDim.x + threadIdx.x;
    if (e == 0) g_total = 0;               // restore invariant
    if (e >= (unsigned)E) return;
    int s = __ldg(ei + e);
    int d = __ldg(ei + E + e);
    int pos = atomicAdd(&g_cur[d], 1);
    g_csr[pos] = s;
}

// ---------------- tensor-core transform: yl = x@Wl^T (fp16), yr = x@Wr^T ----
// mma.sync m16n8k16 f16->f32. B fragments pre-packed in g_Wfrag (reg-cached
// across node tiles, jb-outer). A fragments: direct half2 loads, L1-resident.
template <int LAYER>
__global__ __launch_bounds__(128) void tgemm_kernel(int n) {
    const __half* __restrict__ xin = (LAYER == 1) ? g_xh : g_hh;
    const uint2* __restrict__ Wf = g_Wfrag[LAYER - 1];

    int tid = threadIdx.x;
    int warp = tid >> 5, lane = tid & 31;
    int gid = lane >> 2;      // groupID (row within tile)
    int th  = lane & 3;       // thread-in-group (col pair)
    int ntiles = (n + 15) >> 4;
    int wtile0 = blockIdx.x * 4 + warp;
    int wstride = gridDim.x * 4;

#pragma unroll
    for (int jb = 0; jb < 4; jb++) {
        uint2 B[4][4];
#pragma unroll
        for (int jj = 0; jj < 4; jj++)
#pragma unroll
            for (int t = 0; t < 4; t++)
                B[jj][t] = Wf[((jb * 4 + jj) * 4 + t) * 32 + lane];

        for (int nt = wtile0; nt < ntiles; nt += wstride) {
            int r0 = nt * 16 + gid;
            const __half* xr0 = xin + (size_t)r0 * 64;
            const __half* xr8 = xin + (size_t)(r0 + 8) * 64;
            unsigned A_[4][4];
#pragma unroll
            for (int t = 0; t < 4; t++) {
                int c0 = t * 16 + th * 2;
                A_[t][0] = *(const unsigned*)(xr0 + c0);
                A_[t][1] = *(const unsigned*)(xr8 + c0);
                A_[t][2] = *(const unsigned*)(xr0 + c0 + 8);
                A_[t][3] = *(const unsigned*)(xr8 + c0 + 8);
            }
#pragma unroll
            for (int jj = 0; jj < 4; jj++) {
                int j = jb * 4 + jj;
                float d0 = 0.f, d1 = 0.f, d2 = 0.f, d3 = 0.f;
#pragma unroll
                for (int t = 0; t < 4; t++) {
                    asm volatile(
                        "mma.sync.aligned.m16n8k16.row.col.f32.f16.f16.f32 "
                        "{%0,%1,%2,%3}, {%4,%5,%6,%7}, {%8,%9}, {%0,%1,%2,%3};"
                        : "+f"(d0), "+f"(d1), "+f"(d2), "+f"(d3)
                        : "r"(A_[t][0]), "r"(A_[t][1]), "r"(A_[t][2]), "r"(A_[t][3]),
                          "r"(B[jj][t].x), "r"(B[jj][t].y));
                }
                if (j < 8) {
                    int c = j * 8 + th * 2;
                    __half2 lo = __floats2half2_rn(d0, d1);
                    __half2 hi = __floats2half2_rn(d2, d3);
                    *(__half2*)(g_ylh + (size_t)r0 * 64 + c) = lo;
                    *(__half2*)(g_ylh + (size_t)(r0 + 8) * 64 + c) = hi;
                } else {
                    int c = (j - 8) * 8 + th * 2;
                    *(float2*)(g_yr + (size_t)r0 * 64 + c) = make_float2(d0, d1);
                    *(float2*)(g_yr + (size_t)(r0 + 8) * 64 + c) = make_float2(d2, d3);
                }
            }
        }
    }
}

// ---------------- aggregation epilogue: out = act(mean_j yl_j + yr_v + b) ----
template <int LAYER>
__global__ __launch_bounds__(256) void agg_kernel(const float* __restrict__ bias,
                                                  int n) {
    int tid = threadIdx.x;
    int warp = tid >> 5, lane = tid & 31;
    int v = blockIdx.x * 8 + warp;
    if (v >= n) return;

    const __half2* __restrict__ yl2 = (const __half2*)g_ylh;
    int beg = g_off[v], deg = g_degi[v], end = beg + deg;

    float2 acc = make_float2(0.f, 0.f);
    int j = beg;
    while (j + 32 <= end) {
        int idx = __ldg(g_csr + j + lane);
#pragma unroll
        for (int k = 0; k < 32; k++) {
            int s = __shfl_sync(0xffffffffu, idx, k);
            float2 t = __half22float2(yl2[(size_t)s * 32 + lane]);
            acc.x += t.x; acc.y += t.y;
        }
        j += 32;
    }
    if (j < end) {
        int nb = end - j;
        int idx = __ldg(g_csr + min(j + lane, end - 1));
        int s0 = __shfl_sync(0xffffffffu, idx, 0);
        __half2 t = yl2[(size_t)s0 * 32 + lane];
        for (int k = 1; k < nb; k++) {
            int s = __shfl_sync(0xffffffffu, idx, k);
            __half2 tn = yl2[(size_t)s * 32 + lane];
            float2 tf = __half22float2(t);
            acc.x += tf.x; acc.y += tf.y;
            t = tn;
        }
        float2 tf = __half22float2(t);
        acc.x += tf.x; acc.y += tf.y;
    }

    float inv = g_inv[v];
    float2 yr = ((const float2*)g_yr)[(size_t)v * 32 + lane];
    float2 b2 = make_float2(bias[2 * lane], bias[2 * lane + 1]);
    float2 o;
    o.x = acc.x * inv + yr.x + b2.x;
    o.y = acc.y * inv + yr.y + b2.y;
    if (LAYER == 1) {
        o.x = fmaxf(o.x, 0.f); o.y = fmaxf(o.y, 0.f);
        ((__half2*)g_hh)[(size_t)v * 32 + lane] = __floats2half2_rn(o.x, o.y);
    } else {
        ((__half2*)g_h2h)[(size_t)v * 32 + lane] = __floats2half2_rn(o.x, o.y);
        if (lane == 0) g_degi[v] = 0;     // restore invariant
    }
}

// ---------------- edge-dot classifier (fp16 inputs, fp32 accumulate) --------
__global__ void edge_dot_kernel(const int* __restrict__ ei,
                                float* __restrict__ out, int E) {
    unsigned t = blockIdx.x * blockDim.x + threadIdx.x;
    unsigned e = t >> 3, q = t & 7;
    if (e >= (unsigned)E) return;
    int s = __ldg(ei + e);
    int d = __ldg(ei + E + e);
    const uint4* hs = (const uint4*)(g_h2h + (size_t)s * 64);
    const uint4* hd = (const uint4*)(g_h2h + (size_t)d * 64);
    uint4 ua = hs[q];
    uint4 ub = hd[q];
    float2 a0 = __half22float2(*(__half2*)&ua.x), b0 = __half22float2(*(__half2*)&ub.x);
    float2 a1 = __half22float2(*(__half2*)&ua.y), b1 = __half22float2(*(__half2*)&ub.y);
    float2 a2 = __half22float2(*(__half2*)&ua.z), b2 = __half22float2(*(__half2*)&ub.z);
    float2 a3 = __half22float2(*(__half2*)&ua.w), b3 = __half22float2(*(__half2*)&ub.w);
    float sum = a0.x * b0.x + a0.y * b0.y + a1.x * b1.x + a1.y * b1.y
              + a2.x * b2.x + a2.y * b2.y + a3.x * b3.x + a3.y * b3.y;
    sum += __shfl_xor_sync(0xffffffffu, sum, 1);
    sum += __shfl_xor_sync(0xffffffffu, sum, 2);
    sum += __shfl_xor_sync(0xffffffffu, sum, 4);
    if (q == 0) out[e] = sum;
}

// ---------------- launch ----------------
extern "C" void kernel_launch(void* const* d_in, const int* in_sizes, int n_in,
                              void* d_out, int out_size) {
    const float* emb = (const float*)d_in[0];
    const float* Wl1 = (const float*)d_in[1];
    const float* Wr1 = (const float*)d_in[2];
    const float* b1  = (const float*)d_in[3];
    const float* Wl2 = (const float*)d_in[4];
    const float* Wr2 = (const float*)d_in[5];
    const float* b2  = (const float*)d_in[6];
    const int*   nid = (const int*)d_in[7];
    const int*   ei  = (const int*)d_in[8];
    float* out = (float*)d_out;

    int n = in_sizes[0] / H;       // 100000
    int E = in_sizes[8] / 2;       // 1600000

    static cudaStream_t sB = nullptr;
    static cudaEvent_t evF = nullptr, evJ = nullptr;
    if (!sB) {
        cudaStreamCreateWithFlags(&sB, cudaStreamNonBlocking);
        cudaEventCreateWithFlags(&evF, cudaEventDisableTiming);
        cudaEventCreateWithFlags(&evJ, cudaEventDisableTiming);
    }

    unsigned thr = 256;
    unsigned fb  = ((unsigned)(E > n * 16 ? E : n * 16) + thr - 1) / thr;
    unsigned eb  = ((unsigned)E + thr - 1) / thr;
    unsigned nb  = ((unsigned)n + thr - 1) / thr;
    unsigned agb = ((unsigned)n + 7) / 8;
    unsigned db  = ((unsigned)E * 8 + thr - 1) / thr;

    fused_prep<<<fb, thr>>>((const float4*)emb, nid, Wl1, Wr1, Wl2, Wr2, ei, n, E);

    // fork: CSR build on sB, gemm1 on main stream, join before agg1
    cudaEventRecord(evF, 0);
    cudaStreamWaitEvent(sB, evF, 0);
    alloc_kernel<<<nb, thr, 0, sB>>>(n);
    csr_kernel<<<eb, thr, 0, sB>>>(ei, E);
    cudaEventRecord(evJ, sB);

    tgemm_kernel<1><<<400, 128>>>(n);
    cudaStreamWaitEvent(0, evJ, 0);

    agg_kernel<1><<<agb, thr>>>(b1, n);
    tgemm_kernel<2><<<400, 128>>>(n);
    agg_kernel<2><<<agb, thr>>>(b2, n);
    edge_dot_kernel<<<db, thr>>>(ei, out, E);
}